// round 4
// baseline (speedup 1.0000x reference)
#include <cuda_runtime.h>

// Problem constants
#define BB 4096
#define LL 5
#define DD 128
#define NHH 16
#define NVV 4
#define TT 100
#define FC1 752

// ---------------- kernel 1: features + FC1 -> xc ----------------
#define RB1 8
#define NT1 256

__device__ __align__(16) float g_xc[BB * 256]; // [B][256]: x | user emb

__global__ void __launch_bounds__(NT1)
caser_feat_kernel(const int* __restrict__ d_seq,
                  const int* __restrict__ d_user,
                  const float* __restrict__ d_item_table,
                  const float* __restrict__ d_user_table,
                  const float* __restrict__ d_Wv,
                  const float* __restrict__ d_bv,
                  const float* __restrict__ d_Wh,
                  const float* __restrict__ d_bh,
                  const float* __restrict__ d_W1,
                  const float* __restrict__ d_b1)
{
    __shared__ __align__(16) float s_emb[RB1 * 5 * DD];  // 20KB
    __shared__ __align__(16) float s_z[RB1 * FC1];       // 23.5KB
    __shared__ float s_wv[20], s_bv[4], s_bh[80], s_b1[128];
    __shared__ int   s_seq[RB1 * LL];

    const int tid  = threadIdx.x;
    const int wid  = tid >> 5;
    const int lane = tid & 31;
    const int base = blockIdx.x * RB1;

    // seq ids (independent condition — NT1=256, must not run off the block!)
    if (tid < RB1 * LL) s_seq[tid] = d_seq[base * LL + tid];
    // small weights
    if (tid < 20)       s_wv[tid] = d_Wv[tid];
    else if (tid < 24)  s_bv[tid - 20] = d_bv[tid - 20];
    else if (tid < 104) s_bh[tid - 24] = d_bh[tid - 24];
    else if (tid < 232) s_b1[tid - 104] = d_b1[tid - 104];
    __syncthreads();

    // gather item embeddings: 8 rows x 5 items x 32 float4
    {
        const float4* it4 = (const float4*)d_item_table;
        float4* e4 = (float4*)s_emb;
        for (int i = tid; i < RB1 * LL * 32; i += NT1) {
            int ri = i >> 5, d4 = i & 31;
            e4[i] = it4[(size_t)s_seq[ri] * 32 + d4];
        }
    }
    __syncthreads();

    // vertical conv -> z[:, 0..512)
    for (int o = tid; o < RB1 * NVV * DD; o += NT1) {
        int r = o >> 9;
        int j = o & 511;
        int v = j >> 7;
        int d = j & 127;
        const float* e = s_emb + r * 640 + d;
        float acc = s_bv[v];
        #pragma unroll
        for (int t = 0; t < 5; t++) acc = fmaf(e[t * 128], s_wv[v * 5 + t], acc);
        s_z[r * FC1 + j] = acc;
    }

    // horizontal convs -> z[:, 512..752): warp-per-output, 4-batched
    const int zoff_tab[5] = {512, 592, 656, 704, 736};
    #pragma unroll
    for (int l = 1; l <= 5; l++) {
        const int lout = 6 - l;
        const int zoff = zoff_tab[l - 1];
        const int cnt  = (RB1 * 16 * lout) / 8;    // per warp, %4==0
        const int o0   = wid * cnt;
        for (int u = 0; u < cnt; u += 4) {
            float acc[4];
            #pragma unroll
            for (int q = 0; q < 4; q++) {
                int o = o0 + u + q;
                int r = o / (16 * lout);
                int j = o - r * (16 * lout);
                int f = j / lout;
                int t = j - f * lout;
                const float4* e4 = (const float4*)(s_emb + r * 640 + t * 128);
                const float4* w4 = (const float4*)(d_Wh + (((l - 1) * 16 + f) * 5) * 128);
                float a = 0.f;
                #pragma unroll
                for (int s = 0; s < l; s++) {
                    float4 ev = e4[s * 32 + lane];
                    float4 wv = __ldg(w4 + s * 32 + lane);
                    a += ev.x * wv.x + ev.y * wv.y + ev.z * wv.z + ev.w * wv.w;
                }
                acc[q] = a;
            }
            #pragma unroll
            for (int q = 0; q < 4; q++)
                #pragma unroll
                for (int sft = 16; sft; sft >>= 1)
                    acc[q] += __shfl_xor_sync(0xffffffffu, acc[q], sft);
            if (lane == 0) {
                #pragma unroll
                for (int q = 0; q < 4; q++) {
                    int o = o0 + u + q;
                    int r = o / (16 * lout);
                    int j = o - r * (16 * lout);
                    int f = j / lout;
                    int t = j - f * lout;
                    float h = acc[q] + s_bh[(l - 1) * 16 + f];
                    s_z[r * FC1 + zoff + f * lout + t] = fmaxf(h, 0.f);
                }
            }
        }
    }
    __syncthreads();

    // user-emb gather -> g_xc[:,128..256)
    {
        const float4* ut4 = (const float4*)d_user_table;
        float4* xc4 = (float4*)g_xc;
        for (int o = tid; o < RB1 * 32; o += NT1) {
            int r = o >> 5, d4 = o & 31;
            int u = d_user[base + r];
            xc4[(size_t)(base + r) * 64 + 32 + d4] = ut4[(size_t)u * 32 + d4];
        }
    }

    // FC1: x = relu(z @ W1 + b1) -> g_xc[:,0..128)
    {
        const int d  = tid & 127;
        const int rh = tid >> 7;        // 0..1, 4 rows each
        float acc[4] = {0.f, 0.f, 0.f, 0.f};
        const float* __restrict__ w1p = d_W1 + d;
        const float* zb0 = s_z + rh * 4 * FC1;
        #pragma unroll 2
        for (int k = 0; k < FC1; k += 4) {
            float wa = __ldg(w1p + (k + 0) * 128);
            float wb = __ldg(w1p + (k + 1) * 128);
            float wc = __ldg(w1p + (k + 2) * 128);
            float wd = __ldg(w1p + (k + 3) * 128);
            #pragma unroll
            for (int i = 0; i < 4; i++) {
                float4 zv = *(const float4*)(zb0 + i * FC1 + k);
                acc[i] = fmaf(zv.x, wa, acc[i]);
                acc[i] = fmaf(zv.y, wb, acc[i]);
                acc[i] = fmaf(zv.z, wc, acc[i]);
                acc[i] = fmaf(zv.w, wd, acc[i]);
            }
        }
        float bb = s_b1[d];
        #pragma unroll
        for (int i = 0; i < 4; i++) {
            int r = rh * 4 + i;
            g_xc[(size_t)(base + r) * 256 + d] = fmaxf(acc[i] + bb, 0.f);
        }
    }
}

// ---------------- kernel 2: scoring ----------------
#define NT2 256

__global__ void __launch_bounds__(NT2)
caser_score_kernel(const int* __restrict__ d_items,
                   const float* __restrict__ d_W2,
                   const float* __restrict__ d_b2,
                   float* __restrict__ d_out)
{
    const int wid  = threadIdx.x >> 5;
    const int lane = threadIdx.x & 31;
    const int row  = blockIdx.x * 8 + wid;

    const float4* xc4 = ((const float4*)g_xc) + (size_t)row * 64;
    float4 c0 = xc4[lane];
    float4 c1 = xc4[lane + 32];

    const int* itp = d_items + (size_t)row * TT;
    float* outp = d_out + (size_t)row * TT;

    for (int t = 0; t < TT; t += 4) {
        int it[4];
        #pragma unroll
        for (int q = 0; q < 4; q++) it[q] = __ldg(itp + t + q);
        float acc[4];
        #pragma unroll
        for (int q = 0; q < 4; q++) {
            const float4* w2 = (const float4*)(d_W2 + (size_t)it[q] * 256);
            float4 a0 = __ldg(w2 + lane);
            float4 a1 = __ldg(w2 + lane + 32);
            acc[q] = a0.x * c0.x + a0.y * c0.y + a0.z * c0.z + a0.w * c0.w
                   + a1.x * c1.x + a1.y * c1.y + a1.z * c1.z + a1.w * c1.w;
        }
        #pragma unroll
        for (int q = 0; q < 4; q++)
            #pragma unroll
            for (int sft = 16; sft; sft >>= 1)
                acc[q] += __shfl_xor_sync(0xffffffffu, acc[q], sft);
        if (lane == 0) {
            #pragma unroll
            for (int q = 0; q < 4; q++)
                outp[t + q] = acc[q] + __ldg(d_b2 + it[q]);
        }
    }
}

extern "C" void kernel_launch(void* const* d_in, const int* in_sizes, int n_in,
                              void* d_out, int out_size)
{
    const int*   seq        = (const int*)  d_in[0];
    const int*   user       = (const int*)  d_in[1];
    const int*   items      = (const int*)  d_in[2];
    const float* item_table = (const float*)d_in[3];
    const float* user_table = (const float*)d_in[4];
    const float* Wv         = (const float*)d_in[5];
    const float* bv         = (const float*)d_in[6];
    const float* Wh         = (const float*)d_in[7];
    const float* bh         = (const float*)d_in[8];
    const float* W1         = (const float*)d_in[9];
    const float* b1         = (const float*)d_in[10];
    const float* W2         = (const float*)d_in[11];
    const float* b2         = (const float*)d_in[12];
    (void)in_sizes; (void)n_in; (void)out_size;

    caser_feat_kernel<<<BB / RB1, NT1>>>(seq, user, item_table, user_table,
                                         Wv, bv, Wh, bh, W1, b1);
    caser_score_kernel<<<BB / 8, NT2>>>(items, W2, b2, (float*)d_out);
}

// round 5
// speedup vs baseline: 1.0602x; 1.0602x over previous
#include <cuda_runtime.h>

// Problem constants
#define BB 4096
#define LL 5
#define DD 128
#define NHH 16
#define NVV 4
#define TT 100
#define FC1 752

__device__ __align__(16) float g_xc[BB * 256];  // [B][256]: x | user emb
__device__ __align__(16) float g_z[BB * FC1];   // [B][752]

// ---------------- K1: convolutions + user gather ----------------
#define RB1 4
#define NT1 256

__global__ void __launch_bounds__(NT1)
caser_conv_kernel(const int* __restrict__ d_seq,
                  const int* __restrict__ d_user,
                  const float* __restrict__ d_item_table,
                  const float* __restrict__ d_user_table,
                  const float* __restrict__ d_Wv,
                  const float* __restrict__ d_bv,
                  const float* __restrict__ d_Wh,
                  const float* __restrict__ d_bh)
{
    __shared__ __align__(16) float s_emb[RB1 * 5 * DD];   // 10KB
    __shared__ float s_wv[20], s_bv[4], s_bh[80];
    __shared__ int   s_seq[RB1 * LL];

    const int tid  = threadIdx.x;
    const int wid  = tid >> 5;
    const int lane = tid & 31;
    const int base = blockIdx.x * RB1;

    if (tid < RB1 * LL) s_seq[tid] = d_seq[base * LL + tid];
    if (tid >= 32 && tid < 52)       s_wv[tid - 32] = d_Wv[tid - 32];
    else if (tid >= 52 && tid < 56)  s_bv[tid - 52] = d_bv[tid - 52];
    else if (tid >= 64 && tid < 144) s_bh[tid - 64] = d_bh[tid - 64];
    __syncthreads();

    // gather item embeddings: 4 rows x 5 items x 32 float4
    {
        const float4* it4 = (const float4*)d_item_table;
        float4* e4 = (float4*)s_emb;
        for (int i = tid; i < RB1 * LL * 32; i += NT1) {
            int ri = i >> 5, d4 = i & 31;
            e4[i] = it4[(size_t)s_seq[ri] * 32 + d4];
        }
    }
    // user-emb gather -> g_xc[:,128..256)  (independent of s_emb)
    {
        const float4* ut4 = (const float4*)d_user_table;
        float4* xc4 = (float4*)g_xc;
        for (int o = tid; o < RB1 * 32; o += NT1) {
            int r = o >> 5, d4 = o & 31;
            int u = d_user[base + r];
            xc4[(size_t)(base + r) * 64 + 32 + d4] = ut4[(size_t)u * 32 + d4];
        }
    }
    __syncthreads();

    // vertical conv -> g_z[:, 0..512): 4*512 = 2048 outputs
    for (int o = tid; o < RB1 * NVV * DD; o += NT1) {
        int r = o >> 9;
        int j = o & 511;
        int v = j >> 7;
        int d = j & 127;
        const float* e = s_emb + r * 640 + d;
        float acc = s_bv[v];
        #pragma unroll
        for (int t = 0; t < 5; t++) acc = fmaf(e[t * 128], s_wv[v * 5 + t], acc);
        g_z[(size_t)(base + r) * FC1 + j] = acc;
    }

    // horizontal convs -> g_z[:, 512..752): warp-per-output, 4-batched
    const int zoff_tab[5] = {512, 592, 656, 704, 736};
    #pragma unroll
    for (int l = 1; l <= 5; l++) {
        const int lout = 6 - l;
        const int zoff = zoff_tab[l - 1];
        const int cnt  = (RB1 * 16 * lout) / 8;    // 8*lout per warp, %4==0
        const int o0   = wid * cnt;
        for (int u = 0; u < cnt; u += 4) {
            float acc[4];
            #pragma unroll
            for (int q = 0; q < 4; q++) {
                int o = o0 + u + q;
                int r = o / (16 * lout);
                int j = o - r * (16 * lout);
                int f = j / lout;
                int t = j - f * lout;
                const float4* e4 = (const float4*)(s_emb + r * 640 + t * 128);
                const float4* w4 = (const float4*)(d_Wh + (((l - 1) * 16 + f) * 5) * 128);
                float a = 0.f;
                #pragma unroll
                for (int s = 0; s < l; s++) {
                    float4 ev = e4[s * 32 + lane];
                    float4 wv = __ldg(w4 + s * 32 + lane);
                    a += ev.x * wv.x + ev.y * wv.y + ev.z * wv.z + ev.w * wv.w;
                }
                acc[q] = a;
            }
            #pragma unroll
            for (int q = 0; q < 4; q++)
                #pragma unroll
                for (int sft = 16; sft; sft >>= 1)
                    acc[q] += __shfl_xor_sync(0xffffffffu, acc[q], sft);
            if (lane == 0) {
                #pragma unroll
                for (int q = 0; q < 4; q++) {
                    int o = o0 + u + q;
                    int r = o / (16 * lout);
                    int j = o - r * (16 * lout);
                    int f = j / lout;
                    int t = j - f * lout;
                    float h = acc[q] + s_bh[(l - 1) * 16 + f];
                    g_z[(size_t)(base + r) * FC1 + zoff + f * lout + t] = fmaxf(h, 0.f);
                }
            }
        }
    }
}

// ---------------- K2: FC1 (no smem, broadcast z loads) ----------------
#define RB2 8
#define NT2 256

__global__ void __launch_bounds__(NT2)
caser_fc1_kernel(const float* __restrict__ d_W1,
                 const float* __restrict__ d_b1)
{
    const int tid  = threadIdx.x;
    const int base = blockIdx.x * RB2;
    const int d    = tid & 127;
    const int rh   = tid >> 7;       // 0..1, 4 rows each

    float acc[4] = {0.f, 0.f, 0.f, 0.f};
    const float* __restrict__ w1p = d_W1 + d;
    const float* zb0 = g_z + (size_t)(base + rh * 4) * FC1;
    #pragma unroll 2
    for (int k = 0; k < FC1; k += 4) {
        float wa = __ldg(w1p + (k + 0) * 128);
        float wb = __ldg(w1p + (k + 1) * 128);
        float wc = __ldg(w1p + (k + 2) * 128);
        float wd = __ldg(w1p + (k + 3) * 128);
        #pragma unroll
        for (int i = 0; i < 4; i++) {
            float4 zv = __ldg((const float4*)(zb0 + i * FC1 + k));
            acc[i] = fmaf(zv.x, wa, acc[i]);
            acc[i] = fmaf(zv.y, wb, acc[i]);
            acc[i] = fmaf(zv.z, wc, acc[i]);
            acc[i] = fmaf(zv.w, wd, acc[i]);
        }
    }
    float bb = __ldg(d_b1 + d);
    #pragma unroll
    for (int i = 0; i < 4; i++) {
        int r = rh * 4 + i;
        g_xc[(size_t)(base + r) * 256 + d] = fmaxf(acc[i] + bb, 0.f);
    }
}

// ---------------- K3: scoring (2 rows/block, 25 items/warp) ----------------
#define NT3 256

__global__ void __launch_bounds__(NT3)
caser_score_kernel(const int* __restrict__ d_items,
                   const float* __restrict__ d_W2,
                   const float* __restrict__ d_b2,
                   float* __restrict__ d_out)
{
    const int wid  = threadIdx.x >> 5;
    const int lane = threadIdx.x & 31;
    const int row  = blockIdx.x * 2 + (wid >> 2);
    const int part = wid & 3;                 // quarter of the 100 items

    const float4* xc4 = ((const float4*)g_xc) + (size_t)row * 64;
    float4 c0 = xc4[lane];
    float4 c1 = xc4[lane + 32];

    const int* itp = d_items + (size_t)row * TT + part * 25;
    float* outp = d_out + (size_t)row * TT + part * 25;

    for (int t = 0; t < 25; t += 5) {
        int it[5];
        #pragma unroll
        for (int q = 0; q < 5; q++) it[q] = __ldg(itp + t + q);
        float acc[5];
        #pragma unroll
        for (int q = 0; q < 5; q++) {
            const float4* w2 = (const float4*)(d_W2 + (size_t)it[q] * 256);
            float4 a0 = __ldg(w2 + lane);
            float4 a1 = __ldg(w2 + lane + 32);
            acc[q] = a0.x * c0.x + a0.y * c0.y + a0.z * c0.z + a0.w * c0.w
                   + a1.x * c1.x + a1.y * c1.y + a1.z * c1.z + a1.w * c1.w;
        }
        #pragma unroll
        for (int q = 0; q < 5; q++)
            #pragma unroll
            for (int sft = 16; sft; sft >>= 1)
                acc[q] += __shfl_xor_sync(0xffffffffu, acc[q], sft);
        if (lane == 0) {
            #pragma unroll
            for (int q = 0; q < 5; q++)
                outp[t + q] = acc[q] + __ldg(d_b2 + it[q]);
        }
    }
}

extern "C" void kernel_launch(void* const* d_in, const int* in_sizes, int n_in,
                              void* d_out, int out_size)
{
    const int*   seq        = (const int*)  d_in[0];
    const int*   user       = (const int*)  d_in[1];
    const int*   items      = (const int*)  d_in[2];
    const float* item_table = (const float*)d_in[3];
    const float* user_table = (const float*)d_in[4];
    const float* Wv         = (const float*)d_in[5];
    const float* bv         = (const float*)d_in[6];
    const float* Wh         = (const float*)d_in[7];
    const float* bh         = (const float*)d_in[8];
    const float* W1         = (const float*)d_in[9];
    const float* b1         = (const float*)d_in[10];
    const float* W2         = (const float*)d_in[11];
    const float* b2         = (const float*)d_in[12];
    (void)in_sizes; (void)n_in; (void)out_size;

    caser_conv_kernel<<<BB / RB1, NT1>>>(seq, user, item_table, user_table,
                                         Wv, bv, Wh, bh);
    caser_fc1_kernel<<<BB / RB2, NT2>>>(W1, b1);
    caser_score_kernel<<<BB / 2, NT3>>>(items, W2, b2, (float*)d_out);
}

// round 6
// speedup vs baseline: 1.7321x; 1.6338x over previous
#include <cuda_runtime.h>

#define BB 4096
#define TT 100
#define FC1 752

__device__ __align__(16) float g_xc[BB * 256]; // [B][256]: x | user emb
__device__ __align__(16) float g_z[BB * FC1];  // [B][752]

// ---- packed f32x2 helpers (Blackwell FFMA2 path) ----
__device__ __forceinline__ unsigned long long fma2(unsigned long long a,
                                                   unsigned long long b,
                                                   unsigned long long c) {
    unsigned long long d;
    asm("fma.rn.f32x2 %0, %1, %2, %3;" : "=l"(d) : "l"(a), "l"(b), "l"(c));
    return d;
}
__device__ __forceinline__ unsigned long long dup2(float x) {
    unsigned long long r;
    asm("mov.b64 %0, {%1, %1};" : "=l"(r) : "f"(x));
    return r;
}
__device__ __forceinline__ float2 unpk(unsigned long long v) {
    float2 f;
    asm("mov.b64 {%0, %1}, %2;" : "=f"(f.x), "=f"(f.y) : "l"(v));
    return f;
}

// ---------------- K1: convolutions (warp = row, register-resident) ----------
#define NT1 256

template <int L>
__device__ __forceinline__ void hor_conv(const float4 e[5],
                                         const float4* __restrict__ wh4, // + (L-1)*16*5*32
                                         const float* __restrict__ d_bh,
                                         float* __restrict__ zrow, int lane)
{
    constexpr int LOUT = 6 - L;
    constexpr int ZOFF = 512 + 16 * (6 * (L - 1) - (L * (L - 1)) / 2);
    for (int f = 0; f < 16; f++) {
        float4 w[L];
        #pragma unroll
        for (int s = 0; s < L; s++)
            w[s] = __ldg(wh4 + (f * 5 + s) * 32 + lane);
        float acc[LOUT];
        #pragma unroll
        for (int t = 0; t < LOUT; t++) {
            float a = 0.f;
            #pragma unroll
            for (int s = 0; s < L; s++) {
                a = fmaf(e[t + s].x, w[s].x, a);
                a = fmaf(e[t + s].y, w[s].y, a);
                a = fmaf(e[t + s].z, w[s].z, a);
                a = fmaf(e[t + s].w, w[s].w, a);
            }
            acc[t] = a;
        }
        #pragma unroll
        for (int t = 0; t < LOUT; t++)
            #pragma unroll
            for (int sft = 16; sft; sft >>= 1)
                acc[t] += __shfl_xor_sync(0xffffffffu, acc[t], sft);
        if (lane == 0) {
            float bhv = __ldg(d_bh + (L - 1) * 16 + f);
            #pragma unroll
            for (int t = 0; t < LOUT; t++)
                zrow[ZOFF + f * LOUT + t] = fmaxf(acc[t] + bhv, 0.f);
        }
    }
}

__global__ void __launch_bounds__(NT1)
caser_conv_kernel(const int* __restrict__ d_seq,
                  const int* __restrict__ d_user,
                  const float* __restrict__ d_item_table,
                  const float* __restrict__ d_user_table,
                  const float* __restrict__ d_Wv,
                  const float* __restrict__ d_bv,
                  const float* __restrict__ d_Wh,
                  const float* __restrict__ d_bh)
{
    const int lane = threadIdx.x & 31;
    const int wid  = threadIdx.x >> 5;
    const int row  = blockIdx.x * 8 + wid;

    // emb -> registers: e[t] = item_table[seq[row,t], lane*4 .. +3]
    float4 e[5];
    #pragma unroll
    for (int t = 0; t < 5; t++) {
        int idx = __ldg(d_seq + row * 5 + t);
        e[t] = __ldg((const float4*)d_item_table + (size_t)idx * 32 + lane);
    }
    // user embedding gather -> g_xc[:,128..256)
    {
        int u = __ldg(d_user + row);
        ((float4*)g_xc)[(size_t)row * 64 + 32 + lane] =
            __ldg((const float4*)d_user_table + (size_t)u * 32 + lane);
    }

    float* zrow = g_z + (size_t)row * FC1;

    // vertical conv -> z[:, 0..512)
    #pragma unroll
    for (int v = 0; v < 4; v++) {
        float b = __ldg(d_bv + v);
        float4 acc = {b, b, b, b};
        #pragma unroll
        for (int t = 0; t < 5; t++) {
            float wv = __ldg(d_Wv + v * 5 + t);
            acc.x = fmaf(e[t].x, wv, acc.x);
            acc.y = fmaf(e[t].y, wv, acc.y);
            acc.z = fmaf(e[t].z, wv, acc.z);
            acc.w = fmaf(e[t].w, wv, acc.w);
        }
        ((float4*)zrow)[v * 32 + lane] = acc;
    }

    // horizontal convs -> z[:, 512..752)
    const float4* wh4 = (const float4*)d_Wh;
    hor_conv<1>(e, wh4 + 0 * 16 * 5 * 32, d_bh, zrow, lane);
    hor_conv<2>(e, wh4 + 1 * 16 * 5 * 32, d_bh, zrow, lane);
    hor_conv<3>(e, wh4 + 2 * 16 * 5 * 32, d_bh, zrow, lane);
    hor_conv<4>(e, wh4 + 3 * 16 * 5 * 32, d_bh, zrow, lane);
    hor_conv<5>(e, wh4 + 4 * 16 * 5 * 32, d_bh, zrow, lane);
}

// ---------------- K2: FC1 (float4 W1, 2 rows/warp, packed FFMA2) ------------
#define NT2 256
#define RB2 16

__global__ void __launch_bounds__(NT2)
caser_fc1_kernel(const float* __restrict__ d_W1,
                 const float* __restrict__ d_b1)
{
    __shared__ __align__(16) float s_z[RB2 * FC1];   // 48128 B
    const int tid  = threadIdx.x;
    const int lane = tid & 31;
    const int wid  = tid >> 5;
    const int base = blockIdx.x * RB2;

    // stage z tile (contiguous 16 rows)
    {
        const float4* src = (const float4*)(g_z + (size_t)base * FC1);
        float4* dst = (float4*)s_z;
        for (int i = tid; i < RB2 * FC1 / 4; i += NT2)
            dst[i] = __ldg(src + i);
    }
    __syncthreads();

    const float* z0 = s_z + (wid * 2) * FC1;
    const float* z1 = z0 + FC1;
    const float4* w1v = (const float4*)d_W1;

    unsigned long long a00 = 0, a01 = 0, a10 = 0, a11 = 0;

    for (int k = 0; k < FC1; k += 4) {
        float4 zz0 = *(const float4*)(z0 + k);
        float4 zz1 = *(const float4*)(z1 + k);
        float zs0[4] = {zz0.x, zz0.y, zz0.z, zz0.w};
        float zs1[4] = {zz1.x, zz1.y, zz1.z, zz1.w};
        #pragma unroll
        for (int q = 0; q < 4; q++) {
            float4 w4 = __ldg(w1v + (k + q) * 32 + lane);
            union { float4 f; unsigned long long u[2]; } wu;
            wu.f = w4;
            unsigned long long d0 = dup2(zs0[q]);
            unsigned long long d1 = dup2(zs1[q]);
            a00 = fma2(wu.u[0], d0, a00);
            a01 = fma2(wu.u[1], d0, a01);
            a10 = fma2(wu.u[0], d1, a10);
            a11 = fma2(wu.u[1], d1, a11);
        }
    }

    float4 b4 = __ldg((const float4*)d_b1 + lane);
    float2 p0 = unpk(a00), p1 = unpk(a01);
    float4 x;
    x.x = fmaxf(p0.x + b4.x, 0.f);
    x.y = fmaxf(p0.y + b4.y, 0.f);
    x.z = fmaxf(p1.x + b4.z, 0.f);
    x.w = fmaxf(p1.y + b4.w, 0.f);
    ((float4*)g_xc)[(size_t)(base + wid * 2) * 64 + lane] = x;

    p0 = unpk(a10); p1 = unpk(a11);
    x.x = fmaxf(p0.x + b4.x, 0.f);
    x.y = fmaxf(p0.y + b4.y, 0.f);
    x.z = fmaxf(p1.x + b4.z, 0.f);
    x.w = fmaxf(p1.y + b4.w, 0.f);
    ((float4*)g_xc)[(size_t)(base + wid * 2 + 1) * 64 + lane] = x;
}

// ---------------- K3: scoring (2 rows/block, 25 items/warp) -----------------
#define NT3 256

__global__ void __launch_bounds__(NT3)
caser_score_kernel(const int* __restrict__ d_items,
                   const float* __restrict__ d_W2,
                   const float* __restrict__ d_b2,
                   float* __restrict__ d_out)
{
    const int wid  = threadIdx.x >> 5;
    const int lane = threadIdx.x & 31;
    const int row  = blockIdx.x * 2 + (wid >> 2);
    const int part = wid & 3;

    const float4* xc4 = ((const float4*)g_xc) + (size_t)row * 64;
    float4 c0 = xc4[lane];
    float4 c1 = xc4[lane + 32];

    const int* itp = d_items + (size_t)row * TT + part * 25;
    float* outp = d_out + (size_t)row * TT + part * 25;

    for (int t = 0; t < 25; t += 5) {
        int it[5];
        #pragma unroll
        for (int q = 0; q < 5; q++) it[q] = __ldg(itp + t + q);
        float acc[5];
        #pragma unroll
        for (int q = 0; q < 5; q++) {
            const float4* w2 = (const float4*)(d_W2 + (size_t)it[q] * 256);
            float4 a0 = __ldg(w2 + lane);
            float4 a1 = __ldg(w2 + lane + 32);
            acc[q] = a0.x * c0.x + a0.y * c0.y + a0.z * c0.z + a0.w * c0.w
                   + a1.x * c1.x + a1.y * c1.y + a1.z * c1.z + a1.w * c1.w;
        }
        #pragma unroll
        for (int q = 0; q < 5; q++)
            #pragma unroll
            for (int sft = 16; sft; sft >>= 1)
                acc[q] += __shfl_xor_sync(0xffffffffu, acc[q], sft);
        if (lane == 0) {
            #pragma unroll
            for (int q = 0; q < 5; q++)
                outp[t + q] = acc[q] + __ldg(d_b2 + it[q]);
        }
    }
}

extern "C" void kernel_launch(void* const* d_in, const int* in_sizes, int n_in,
                              void* d_out, int out_size)
{
    const int*   seq        = (const int*)  d_in[0];
    const int*   user       = (const int*)  d_in[1];
    const int*   items      = (const int*)  d_in[2];
    const float* item_table = (const float*)d_in[3];
    const float* user_table = (const float*)d_in[4];
    const float* Wv         = (const float*)d_in[5];
    const float* bv         = (const float*)d_in[6];
    const float* Wh         = (const float*)d_in[7];
    const float* bh         = (const float*)d_in[8];
    const float* W1         = (const float*)d_in[9];
    const float* b1         = (const float*)d_in[10];
    const float* W2         = (const float*)d_in[11];
    const float* b2         = (const float*)d_in[12];
    (void)in_sizes; (void)n_in; (void)out_size;

    caser_conv_kernel<<<BB / 8, NT1>>>(seq, user, item_table, user_table,
                                       Wv, bv, Wh, bh);
    caser_fc1_kernel<<<BB / RB2, NT2>>>(W1, b1);
    caser_score_kernel<<<BB / 2, NT3>>>(items, W2, b2, (float*)d_out);
}

// round 7
// speedup vs baseline: 2.0533x; 1.1855x over previous
#include <cuda_runtime.h>

#define BB 4096
#define TT 100
#define FC1 752

__device__ __align__(16) float g_xc[BB * 256]; // [B][256]: x | user emb
__device__ __align__(16) float g_z[BB * FC1];  // [B][752]

// ---- packed f32x2 helpers ----
__device__ __forceinline__ unsigned long long fma2(unsigned long long a,
                                                   unsigned long long b,
                                                   unsigned long long c) {
    unsigned long long d;
    asm("fma.rn.f32x2 %0, %1, %2, %3;" : "=l"(d) : "l"(a), "l"(b), "l"(c));
    return d;
}
__device__ __forceinline__ unsigned long long dup2(float x) {
    unsigned long long r;
    asm("mov.b64 %0, {%1, %1};" : "=l"(r) : "f"(x));
    return r;
}
__device__ __forceinline__ float2 unpk(unsigned long long v) {
    float2 f;
    asm("mov.b64 {%0, %1}, %2;" : "=f"(f.x), "=f"(f.y) : "l"(v));
    return f;
}

// ================= K1: conv (2 rows/warp, butterfly reduce) =================
#define NT1 128   // 4 warps/block, 8 rows/block

// Butterfly transpose-reduce: 31 shuffles. On exit, lane L's v[0] holds the
// warp-wide total of accumulator slot L.
__device__ __forceinline__ void btf32(float (&v)[32], int lane) {
    #pragma unroll
    for (int s = 16; s >= 1; s >>= 1) {
        const bool up = (lane & s) != 0;
        #pragma unroll
        for (int i = 0; i < s; i++) {
            float lo = v[i], hi = v[i + s];
            float give = up ? lo : hi;
            float r = __shfl_xor_sync(0xffffffffu, give, s);
            v[i] = (up ? hi : lo) + r;
        }
    }
}

// One group: filter-length L_, t-offsets T0..T0+NT-1 (NT in {1,2}),
// 16 filters -> up to 32 outputs, for 2 rows.
template <int L_, int T0, int NT>
__device__ __forceinline__ void hor_group(const float4 (&e)[2][5],
                                          const float4* __restrict__ wh4,
                                          const float* __restrict__ d_bh,
                                          float* __restrict__ z0,
                                          float* __restrict__ z1,
                                          int lane)
{
    constexpr int LOUT = 6 - L_;
    constexpr int ZOFF = 512 + 16 * (6 * (L_ - 1) - (L_ * (L_ - 1)) / 2);
    float v0[32], v1[32];
    if (NT == 1) {  // upper slots never written -> must be zero for butterfly
        #pragma unroll
        for (int i = 16; i < 32; i++) { v0[i] = 0.f; v1[i] = 0.f; }
    }
    #pragma unroll
    for (int f = 0; f < 16; f++) {
        float4 w[L_];
        #pragma unroll
        for (int s = 0; s < L_; s++)
            w[s] = __ldg(wh4 + ((L_ - 1) * 80 + f * 5 + s) * 32 + lane);
        #pragma unroll
        for (int tp = 0; tp < NT; tp++) {
            const int a = (NT == 2) ? (f * 2 + tp) : f;
            float a0 = 0.f, a1 = 0.f;
            #pragma unroll
            for (int s = 0; s < L_; s++) {
                const float4 ww = w[s];
                const float4 e0 = e[0][T0 + tp + s];
                const float4 e1 = e[1][T0 + tp + s];
                a0 = fmaf(e0.x, ww.x, a0); a0 = fmaf(e0.y, ww.y, a0);
                a0 = fmaf(e0.z, ww.z, a0); a0 = fmaf(e0.w, ww.w, a0);
                a1 = fmaf(e1.x, ww.x, a1); a1 = fmaf(e1.y, ww.y, a1);
                a1 = fmaf(e1.z, ww.z, a1); a1 = fmaf(e1.w, ww.w, a1);
            }
            v0[a] = a0; v1[a] = a1;
        }
    }
    btf32(v0, lane);
    btf32(v1, lane);
    if (NT == 2 || lane < 16) {
        const int f = (NT == 2) ? (lane >> 1) : lane;
        const int t = T0 + ((NT == 2) ? (lane & 1) : 0);
        const float b = __ldg(d_bh + (L_ - 1) * 16 + f);
        z0[ZOFF + f * LOUT + t] = fmaxf(v0[0] + b, 0.f);
        z1[ZOFF + f * LOUT + t] = fmaxf(v1[0] + b, 0.f);
    }
}

__global__ void __launch_bounds__(NT1)
caser_conv_kernel(const int* __restrict__ d_seq,
                  const int* __restrict__ d_user,
                  const float* __restrict__ d_item_table,
                  const float* __restrict__ d_user_table,
                  const float* __restrict__ d_Wv,
                  const float* __restrict__ d_bv,
                  const float* __restrict__ d_Wh,
                  const float* __restrict__ d_bh)
{
    const int lane = threadIdx.x & 31;
    const int wid  = threadIdx.x >> 5;
    const int r0   = (blockIdx.x * 4 + wid) * 2;   // rows r0, r0+1

    // emb -> registers for both rows
    float4 e[2][5];
    #pragma unroll
    for (int r = 0; r < 2; r++)
        #pragma unroll
        for (int t = 0; t < 5; t++) {
            int idx = __ldg(d_seq + (r0 + r) * 5 + t);
            e[r][t] = __ldg((const float4*)d_item_table + (size_t)idx * 32 + lane);
        }

    // user embedding gather -> g_xc[:,128..256)
    #pragma unroll
    for (int r = 0; r < 2; r++) {
        int u = __ldg(d_user + r0 + r);
        ((float4*)g_xc)[(size_t)(r0 + r) * 64 + 32 + lane] =
            __ldg((const float4*)d_user_table + (size_t)u * 32 + lane);
    }

    float* z0 = g_z + (size_t)r0 * FC1;
    float* z1 = z0 + FC1;

    // vertical conv -> z[:, 0..512)
    #pragma unroll
    for (int v = 0; v < 4; v++) {
        float b = __ldg(d_bv + v);
        float4 a0 = {b, b, b, b}, a1 = {b, b, b, b};
        #pragma unroll
        for (int t = 0; t < 5; t++) {
            float wv = __ldg(d_Wv + v * 5 + t);
            a0.x = fmaf(e[0][t].x, wv, a0.x); a0.y = fmaf(e[0][t].y, wv, a0.y);
            a0.z = fmaf(e[0][t].z, wv, a0.z); a0.w = fmaf(e[0][t].w, wv, a0.w);
            a1.x = fmaf(e[1][t].x, wv, a1.x); a1.y = fmaf(e[1][t].y, wv, a1.y);
            a1.z = fmaf(e[1][t].z, wv, a1.z); a1.w = fmaf(e[1][t].w, wv, a1.w);
        }
        ((float4*)z0)[v * 32 + lane] = a0;
        ((float4*)z1)[v * 32 + lane] = a1;
    }

    // horizontal convs -> z[:, 512..752)
    const float4* wh4 = (const float4*)d_Wh;
    hor_group<1, 0, 2>(e, wh4, d_bh, z0, z1, lane);
    hor_group<1, 2, 2>(e, wh4, d_bh, z0, z1, lane);
    hor_group<1, 4, 1>(e, wh4, d_bh, z0, z1, lane);
    hor_group<2, 0, 2>(e, wh4, d_bh, z0, z1, lane);
    hor_group<2, 2, 2>(e, wh4, d_bh, z0, z1, lane);
    hor_group<3, 0, 2>(e, wh4, d_bh, z0, z1, lane);
    hor_group<3, 2, 1>(e, wh4, d_bh, z0, z1, lane);
    hor_group<4, 0, 2>(e, wh4, d_bh, z0, z1, lane);
    hor_group<5, 0, 1>(e, wh4, d_bh, z0, z1, lane);
}

// ================= K2: FC1 (float4 W1, 2 rows/warp, packed FFMA2) ===========
#define NT2 256
#define RB2 16

__global__ void __launch_bounds__(NT2)
caser_fc1_kernel(const float* __restrict__ d_W1,
                 const float* __restrict__ d_b1)
{
    __shared__ __align__(16) float s_z[RB2 * FC1];
    const int tid  = threadIdx.x;
    const int lane = tid & 31;
    const int wid  = tid >> 5;
    const int base = blockIdx.x * RB2;

    {
        const float4* src = (const float4*)(g_z + (size_t)base * FC1);
        float4* dst = (float4*)s_z;
        for (int i = tid; i < RB2 * FC1 / 4; i += NT2)
            dst[i] = __ldg(src + i);
    }
    __syncthreads();

    const float* z0 = s_z + (wid * 2) * FC1;
    const float* z1 = z0 + FC1;
    const float4* w1v = (const float4*)d_W1;

    unsigned long long a00 = 0, a01 = 0, a10 = 0, a11 = 0;

    for (int k = 0; k < FC1; k += 4) {
        float4 zz0 = *(const float4*)(z0 + k);
        float4 zz1 = *(const float4*)(z1 + k);
        float zs0[4] = {zz0.x, zz0.y, zz0.z, zz0.w};
        float zs1[4] = {zz1.x, zz1.y, zz1.z, zz1.w};
        #pragma unroll
        for (int q = 0; q < 4; q++) {
            float4 w4 = __ldg(w1v + (k + q) * 32 + lane);
            union { float4 f; unsigned long long u[2]; } wu;
            wu.f = w4;
            unsigned long long d0 = dup2(zs0[q]);
            unsigned long long d1 = dup2(zs1[q]);
            a00 = fma2(wu.u[0], d0, a00);
            a01 = fma2(wu.u[1], d0, a01);
            a10 = fma2(wu.u[0], d1, a10);
            a11 = fma2(wu.u[1], d1, a11);
        }
    }

    float4 b4 = __ldg((const float4*)d_b1 + lane);
    float2 p0 = unpk(a00), p1 = unpk(a01);
    float4 x;
    x.x = fmaxf(p0.x + b4.x, 0.f);
    x.y = fmaxf(p0.y + b4.y, 0.f);
    x.z = fmaxf(p1.x + b4.z, 0.f);
    x.w = fmaxf(p1.y + b4.w, 0.f);
    ((float4*)g_xc)[(size_t)(base + wid * 2) * 64 + lane] = x;

    p0 = unpk(a10); p1 = unpk(a11);
    x.x = fmaxf(p0.x + b4.x, 0.f);
    x.y = fmaxf(p0.y + b4.y, 0.f);
    x.z = fmaxf(p1.x + b4.z, 0.f);
    x.w = fmaxf(p1.y + b4.w, 0.f);
    ((float4*)g_xc)[(size_t)(base + wid * 2 + 1) * 64 + lane] = x;
}

// ================= K3: scoring =============================================
#define NT3 256

__global__ void __launch_bounds__(NT3)
caser_score_kernel(const int* __restrict__ d_items,
                   const float* __restrict__ d_W2,
                   const float* __restrict__ d_b2,
                   float* __restrict__ d_out)
{
    const int wid  = threadIdx.x >> 5;
    const int lane = threadIdx.x & 31;
    const int row  = blockIdx.x * 2 + (wid >> 2);
    const int part = wid & 3;

    const float4* xc4 = ((const float4*)g_xc) + (size_t)row * 64;
    float4 c0 = xc4[lane];
    float4 c1 = xc4[lane + 32];

    const int* itp = d_items + (size_t)row * TT + part * 25;
    float* outp = d_out + (size_t)row * TT + part * 25;

    for (int t = 0; t < 25; t += 5) {
        int it[5];
        #pragma unroll
        for (int q = 0; q < 5; q++) it[q] = __ldg(itp + t + q);
        float acc[5];
        #pragma unroll
        for (int q = 0; q < 5; q++) {
            const float4* w2 = (const float4*)(d_W2 + (size_t)it[q] * 256);
            float4 a0 = __ldg(w2 + lane);
            float4 a1 = __ldg(w2 + lane + 32);
            acc[q] = a0.x * c0.x + a0.y * c0.y + a0.z * c0.z + a0.w * c0.w
                   + a1.x * c1.x + a1.y * c1.y + a1.z * c1.z + a1.w * c1.w;
        }
        #pragma unroll
        for (int q = 0; q < 5; q++)
            #pragma unroll
            for (int sft = 16; sft; sft >>= 1)
                acc[q] += __shfl_xor_sync(0xffffffffu, acc[q], sft);
        if (lane == 0) {
            #pragma unroll
            for (int q = 0; q < 5; q++)
                outp[t + q] = acc[q] + __ldg(d_b2 + it[q]);
        }
    }
}

extern "C" void kernel_launch(void* const* d_in, const int* in_sizes, int n_in,
                              void* d_out, int out_size)
{
    const int*   seq        = (const int*)  d_in[0];
    const int*   user       = (const int*)  d_in[1];
    const int*   items      = (const int*)  d_in[2];
    const float* item_table = (const float*)d_in[3];
    const float* user_table = (const float*)d_in[4];
    const float* Wv         = (const float*)d_in[5];
    const float* bv         = (const float*)d_in[6];
    const float* Wh         = (const float*)d_in[7];
    const float* bh         = (const float*)d_in[8];
    const float* W1         = (const float*)d_in[9];
    const float* b1         = (const float*)d_in[10];
    const float* W2         = (const float*)d_in[11];
    const float* b2         = (const float*)d_in[12];
    (void)in_sizes; (void)n_in; (void)out_size;

    caser_conv_kernel<<<BB / 8, NT1>>>(seq, user, item_table, user_table,
                                       Wv, bv, Wh, bh);
    caser_fc1_kernel<<<BB / RB2, NT2>>>(W1, b1);
    caser_score_kernel<<<BB / 2, NT3>>>(items, W2, b2, (float*)d_out);
}